// round 15
// baseline (speedup 1.0000x reference)
#include <cuda_runtime.h>

#define NN 100000
#define NE 1600000
#define NB ((NN + 255) / 256)   // 391 blocks for node-sized kernels

// ---------------- scratch (device globals; no allocation allowed) ----------
__device__ __align__(128) int   g_deg[2 * NN];        // [0,NN): out-deg, [NN,2NN): in-deg
__device__ __align__(128) float g_onorm[NN];
__device__ __align__(128) float g_inorm[NN];
__device__ __align__(128) float g_h1[(size_t)NN * 64];    // (x*onorm)@W1
__device__ __align__(128) float g_agg1[(size_t)NN * 64];  // sum over in-edges of h1[src]
__device__ __align__(128) float g_h2[(size_t)NN * 40];    // layer-2 transformed feats
__device__ __align__(128) int   g_csr[NE];                // src ids grouped by dst
__device__ __align__(128) int   g_rowstart[NN];
__device__ __align__(128) int   g_cursor[NN];
__device__ __align__(128) int   g_bsum[NB + 1];
__device__ __align__(128) int   g_bpre[NB + 1];

// ---------------- packed f32x2 helpers (sm_103a FFMA2 path) -----------------
__device__ __forceinline__ unsigned long long pack2(float x) {
    unsigned long long r;
    asm("mov.b64 %0, {%1, %1};" : "=l"(r) : "f"(x));
    return r;
}
__device__ __forceinline__ void ffma2(unsigned long long& d,
                                      unsigned long long a, unsigned long long b) {
    asm("fma.rn.f32x2 %0, %1, %2, %0;" : "+l"(d) : "l"(a), "l"(b));
}
__device__ __forceinline__ float2 unpack2(unsigned long long v) {
    float2 f;
    asm("mov.b64 {%0, %1}, %2;" : "=f"(f.x), "=f"(f.y) : "l"(v));
    return f;
}

// ---------------- degrees ----------------
__global__ void k_degree(const int* __restrict__ src, const int* __restrict__ dst) {
    int i = blockIdx.x * 256 + threadIdx.x;
    if (i < NE) {
        atomicAdd(&g_deg[__ldg(&src[i])], 1);
        atomicAdd(&g_deg[NN + __ldg(&dst[i])], 1);
    }
}

__global__ void k_norm() {
    int i = blockIdx.x * 256 + threadIdx.x;
    if (i < NN) {
        g_onorm[i] = rsqrtf(fmaxf((float)g_deg[i], 1.0f));
        g_inorm[i] = rsqrtf(fmaxf((float)g_deg[NN + i], 1.0f));
    }
}

// ---------------- CSR build: 3-step block scan of in-degree -----------------
__global__ void k_scan_block() {
    __shared__ int s[256];
    int n = blockIdx.x * 256 + threadIdx.x;
    int v = (n < NN) ? g_deg[NN + n] : 0;
    s[threadIdx.x] = v;
    __syncthreads();
    for (int off = 128; off > 0; off >>= 1) {
        if (threadIdx.x < off) s[threadIdx.x] += s[threadIdx.x + off];
        __syncthreads();
    }
    if (threadIdx.x == 0) g_bsum[blockIdx.x] = s[0];
}

// parallel top-level scan: 1 block, 512 threads (NB=391 fits).
// All shfls run with full-warp participation (divergent masks deadlock).
__global__ void k_scan_top() {
    __shared__ int wsum[16];
    int t = threadIdx.x;
    int lane = t & 31, wid = t >> 5;
    int v = (t < NB) ? g_bsum[t] : 0;
    int x = v;
#pragma unroll
    for (int o = 1; o < 32; o <<= 1) {
        int y = __shfl_up_sync(0xffffffffu, x, o);
        if (lane >= o) x += y;
    }
    if (lane == 31) wsum[wid] = x;
    __syncthreads();
    if (wid == 0) {
        int s = (lane < 16) ? wsum[lane] : 0;
#pragma unroll
        for (int o = 1; o < 16; o <<= 1) {
            int y = __shfl_up_sync(0xffffffffu, s, o);
            if (lane >= o) s += y;
        }
        if (lane < 16) wsum[lane] = s;
    }
    __syncthreads();
    int base = (wid > 0) ? wsum[wid - 1] : 0;
    if (t < NB) g_bpre[t] = base + x - v;   // exclusive prefix of block sums
}

__global__ void k_scan_apply() {
    __shared__ int s[256];
    int n = blockIdx.x * 256 + threadIdx.x;
    int v = (n < NN) ? g_deg[NN + n] : 0;
    s[threadIdx.x] = v;
    __syncthreads();
    for (int off = 1; off < 256; off <<= 1) {
        int t = (threadIdx.x >= off) ? s[threadIdx.x - off] : 0;
        __syncthreads();
        s[threadIdx.x] += t;
        __syncthreads();
    }
    int excl = s[threadIdx.x] - v;
    int rs = g_bpre[blockIdx.x] + excl;
    if (n < NN) { g_rowstart[n] = rs; g_cursor[n] = rs; }
}

__global__ void k_build(const int* __restrict__ src, const int* __restrict__ dst) {
    int e = blockIdx.x * 256 + threadIdx.x;
    if (e < NE) {
        int d = __ldg(&dst[e]);
        int p = atomicAdd(&g_cursor[d], 1);
        g_csr[p] = __ldg(&src[e]);
    }
}

// ---------------- GEMM1: h1 = (x * onorm) @ W1   [100k x 256]@[256 x 64] ----
// Block = 256 threads = 8 warps, covers 128 nodes.
// Warp (h, cg): h = nodes half (64 nodes, 2 per lane), cg = 16-column group.
// KEY: all 32 lanes of a warp read the SAME W address -> broadcast LDS (1 wf).
// x comes from a pad-65 smem tile (per-lane scalar LDS, conflict-free).
// Math: packed f32x2 FFMA2; 16 FFMA2 + 4 LDS.128 + 2 LDS.32 per warp per k.
__global__ void __launch_bounds__(256, 2)
k_gemm1(const float* __restrict__ x, const float* __restrict__ W1) {
    extern __shared__ float smem[];
    float* sW = smem;                 // 256*64 floats = 64KB
    float* sx = smem + 256 * 64;      // 128 nodes * 65 floats = 33.28KB

    for (int i = threadIdx.x; i < 256 * 64 / 4; i += 256)
        reinterpret_cast<float4*>(sW)[i] = reinterpret_cast<const float4*>(W1)[i];

    int lane = threadIdx.x & 31;
    int w = threadIdx.x >> 5;
    int cg = (w & 3) * 16;                 // column group: 0/16/32/48
    int nloc0 = (w >> 2) * 64 + lane;      // local node (first of pair)
    int nloc1 = nloc0 + 32;
    int gn0 = blockIdx.x * 128 + nloc0;
    int gn1 = blockIdx.x * 128 + nloc1;

    unsigned long long acc0[8], acc1[8];   // 2 nodes x 16 cols (8 f32x2)
#pragma unroll
    for (int p = 0; p < 8; p++) { acc0[p] = 0ULL; acc1[p] = 0ULL; }

    for (int chunk = 0; chunk < 4; chunk++) {
        __syncthreads();   // W ready (iter 0) / sx no longer in use (iters 1+)
        // stage x tile: 128 nodes x 64 k, coalesced LDG.128, scalar STS (pad 65)
        for (int i = threadIdx.x; i < 128 * 16; i += 256) {
            int node = i >> 4, q = i & 15;
            int gn = blockIdx.x * 128 + node; if (gn >= NN) gn = NN - 1;
            float4 v = __ldg(reinterpret_cast<const float4*>(
                x + (size_t)gn * 256 + chunk * 64 + q * 4));
            float* d = &sx[node * 65 + q * 4];
            d[0] = v.x; d[1] = v.y; d[2] = v.z; d[3] = v.w;
        }
        __syncthreads();

        const float* xp0 = &sx[nloc0 * 65];
        const float* xp1 = &sx[nloc1 * 65];
        const float* wbase = &sW[chunk * 64 * 64 + cg];
#pragma unroll 8
        for (int k = 0; k < 64; k++) {
            unsigned long long p0 = pack2(xp0[k]);
            unsigned long long p1 = pack2(xp1[k]);
            const ulonglong2* wr =
                reinterpret_cast<const ulonglong2*>(wbase + k * 64);
            ulonglong2 wa = wr[0];   // cols cg+0..3
            ulonglong2 wb = wr[1];   // cols cg+4..7
            ulonglong2 wc = wr[2];   // cols cg+8..11
            ulonglong2 wd = wr[3];   // cols cg+12..15
            ffma2(acc0[0], p0, wa.x); ffma2(acc0[1], p0, wa.y);
            ffma2(acc0[2], p0, wb.x); ffma2(acc0[3], p0, wb.y);
            ffma2(acc0[4], p0, wc.x); ffma2(acc0[5], p0, wc.y);
            ffma2(acc0[6], p0, wd.x); ffma2(acc0[7], p0, wd.y);
            ffma2(acc1[0], p1, wa.x); ffma2(acc1[1], p1, wa.y);
            ffma2(acc1[2], p1, wb.x); ffma2(acc1[3], p1, wb.y);
            ffma2(acc1[4], p1, wc.x); ffma2(acc1[5], p1, wc.y);
            ffma2(acc1[6], p1, wd.x); ffma2(acc1[7], p1, wd.y);
        }
    }

    if (gn0 < NN) {
        float nrm = g_onorm[gn0];
        float4* o = reinterpret_cast<float4*>(&g_h1[(size_t)gn0 * 64 + cg]);
#pragma unroll
        for (int q = 0; q < 4; q++) {
            float2 lo = unpack2(acc0[q * 2 + 0]);
            float2 hi = unpack2(acc0[q * 2 + 1]);
            o[q] = make_float4(lo.x * nrm, lo.y * nrm, hi.x * nrm, hi.y * nrm);
        }
    }
    if (gn1 < NN) {
        float nrm = g_onorm[gn1];
        float4* o = reinterpret_cast<float4*>(&g_h1[(size_t)gn1 * 64 + cg]);
#pragma unroll
        for (int q = 0; q < 4; q++) {
            float2 lo = unpack2(acc1[q * 2 + 0]);
            float2 hi = unpack2(acc1[q * 2 + 1]);
            o[q] = make_float4(lo.x * nrm, lo.y * nrm, hi.x * nrm, hi.y * nrm);
        }
    }
}

#define GEMM1_SMEM (256 * 64 * 4 + 128 * 65 * 4)

// ---------------- agg1: warp per node, 2 groups of 16, 2x unroll ------------
__global__ void k_agg1() {
    int w = (blockIdx.x * 256 + threadIdx.x) >> 5;
    if (w >= NN) return;
    int lane = threadIdx.x & 31;
    int grp = lane >> 4, c = lane & 15;

    int beg = __ldg(&g_rowstart[w]);
    int end = beg + __ldg(&g_deg[NN + w]);

    float4 a0 = make_float4(0.f, 0.f, 0.f, 0.f);
    float4 a1 = make_float4(0.f, 0.f, 0.f, 0.f);
    int j = beg + grp;
    for (; j + 2 < end; j += 4) {
        int s0 = __ldg(&g_csr[j]);
        int s1 = __ldg(&g_csr[j + 2]);
        float4 v0 = *reinterpret_cast<const float4*>(&g_h1[(size_t)s0 * 64 + c * 4]);
        float4 v1 = *reinterpret_cast<const float4*>(&g_h1[(size_t)s1 * 64 + c * 4]);
        a0.x += v0.x; a0.y += v0.y; a0.z += v0.z; a0.w += v0.w;
        a1.x += v1.x; a1.y += v1.y; a1.z += v1.z; a1.w += v1.w;
    }
    if (j < end) {
        int s0 = __ldg(&g_csr[j]);
        float4 v0 = *reinterpret_cast<const float4*>(&g_h1[(size_t)s0 * 64 + c * 4]);
        a0.x += v0.x; a0.y += v0.y; a0.z += v0.z; a0.w += v0.w;
    }
    float4 acc = make_float4(a0.x + a1.x, a0.y + a1.y, a0.z + a1.z, a0.w + a1.w);

    acc.x += __shfl_down_sync(0xffffffffu, acc.x, 16);
    acc.y += __shfl_down_sync(0xffffffffu, acc.y, 16);
    acc.z += __shfl_down_sync(0xffffffffu, acc.z, 16);
    acc.w += __shfl_down_sync(0xffffffffu, acc.w, 16);
    if (lane < 16)
        *reinterpret_cast<float4*>(&g_agg1[(size_t)w * 64 + c * 4]) = acc;
}

// ---------------- GEMM2 (fused): h2 = ((agg1*inorm + b1) * onorm) @ W2 ------
__global__ void k_gemm2(const float* __restrict__ W2, const float* __restrict__ b1) {
    __shared__ float sW[64 * 40];
    __shared__ float sb[64];
    for (int i = threadIdx.x; i < 64 * 40; i += 256) sW[i] = W2[i];
    if (threadIdx.x < 64) sb[threadIdx.x] = b1[threadIdx.x];
    __syncthreads();

    int n = blockIdx.x * 256 + threadIdx.x;
    if (n >= NN) return;
    float ni = g_inorm[n], no = g_onorm[n];

    float acc[40];
#pragma unroll
    for (int j = 0; j < 40; j++) acc[j] = 0.f;

    const float4* ar = reinterpret_cast<const float4*>(&g_agg1[(size_t)n * 64]);
#pragma unroll 4
    for (int k4 = 0; k4 < 16; k4++) {
        float4 a = ar[k4];
        float av[4] = {a.x, a.y, a.z, a.w};
#pragma unroll
        for (int c = 0; c < 4; c++) {
            int k = k4 * 4 + c;
            float xv = av[c] * ni + sb[k];
            const float4* wr = reinterpret_cast<const float4*>(&sW[k * 40]);
#pragma unroll
            for (int q = 0; q < 10; q++) {
                float4 w = wr[q];
                acc[q * 4 + 0] += xv * w.x;
                acc[q * 4 + 1] += xv * w.y;
                acc[q * 4 + 2] += xv * w.z;
                acc[q * 4 + 3] += xv * w.w;
            }
        }
    }

    float4* o = reinterpret_cast<float4*>(&g_h2[(size_t)n * 40]);
#pragma unroll
    for (int q = 0; q < 10; q++)
        o[q] = make_float4(acc[q*4+0]*no, acc[q*4+1]*no, acc[q*4+2]*no, acc[q*4+3]*no);
}

// ---------------- agg2: warp per node, 3 groups of 10, 2x unroll ------------
__global__ void k_agg2(float* __restrict__ out, const float* __restrict__ b2) {
    int w = (blockIdx.x * 256 + threadIdx.x) >> 5;
    if (w >= NN) return;
    int lane = threadIdx.x & 31;
    int grp = lane / 10;             // 0,1,2 active; lanes 30,31 idle
    int c = lane - grp * 10;

    int beg = __ldg(&g_rowstart[w]);
    int end = beg + __ldg(&g_deg[NN + w]);

    float4 a0 = make_float4(0.f, 0.f, 0.f, 0.f);
    float4 a1 = make_float4(0.f, 0.f, 0.f, 0.f);
    if (grp < 3) {
        int j = beg + grp;
        for (; j + 3 < end; j += 6) {
            int s0 = __ldg(&g_csr[j]);
            int s1 = __ldg(&g_csr[j + 3]);
            float4 v0 = *reinterpret_cast<const float4*>(&g_h2[(size_t)s0 * 40 + c * 4]);
            float4 v1 = *reinterpret_cast<const float4*>(&g_h2[(size_t)s1 * 40 + c * 4]);
            a0.x += v0.x; a0.y += v0.y; a0.z += v0.z; a0.w += v0.w;
            a1.x += v1.x; a1.y += v1.y; a1.z += v1.z; a1.w += v1.w;
        }
        if (j < end) {
            int s0 = __ldg(&g_csr[j]);
            float4 v0 = *reinterpret_cast<const float4*>(&g_h2[(size_t)s0 * 40 + c * 4]);
            a0.x += v0.x; a0.y += v0.y; a0.z += v0.z; a0.w += v0.w;
        }
    }
    float4 acc = make_float4(a0.x + a1.x, a0.y + a1.y, a0.z + a1.z, a0.w + a1.w);

    float ax10 = __shfl_down_sync(0xffffffffu, acc.x, 10);
    float ay10 = __shfl_down_sync(0xffffffffu, acc.y, 10);
    float az10 = __shfl_down_sync(0xffffffffu, acc.z, 10);
    float aw10 = __shfl_down_sync(0xffffffffu, acc.w, 10);
    float ax20 = __shfl_down_sync(0xffffffffu, acc.x, 20);
    float ay20 = __shfl_down_sync(0xffffffffu, acc.y, 20);
    float az20 = __shfl_down_sync(0xffffffffu, acc.z, 20);
    float aw20 = __shfl_down_sync(0xffffffffu, acc.w, 20);
    if (lane < 10) {
        float ni = g_inorm[w];
        float4 bb = __ldg(reinterpret_cast<const float4*>(b2) + c);
        float4 r;
        r.x = (acc.x + ax10 + ax20) * ni + bb.x;
        r.y = (acc.y + ay10 + ay20) * ni + bb.y;
        r.z = (acc.z + az10 + az20) * ni + bb.z;
        r.w = (acc.w + aw10 + aw20) * ni + bb.w;
        *reinterpret_cast<float4*>(out + (size_t)w * 40 + c * 4) = r;
    }
}

extern "C" void kernel_launch(void* const* d_in, const int* in_sizes, int n_in,
                              void* d_out, int out_size) {
    const float* x   = (const float*)d_in[0];
    const int*   src = (const int*)d_in[1];
    const int*   dst = (const int*)d_in[2];
    const float* W1  = (const float*)d_in[3];
    const float* b1  = (const float*)d_in[4];
    const float* W2  = (const float*)d_in[5];
    const float* b2  = (const float*)d_in[6];
    float* out = (float*)d_out;

    void* p_deg;
    cudaGetSymbolAddress(&p_deg, g_deg);
    cudaMemsetAsync(p_deg, 0, sizeof(int) * 2 * NN, 0);

    cudaFuncSetAttribute(k_gemm1, cudaFuncAttributeMaxDynamicSharedMemorySize, GEMM1_SMEM);

    k_degree<<<(NE + 255) / 256, 256>>>(src, dst);
    k_norm<<<NB, 256>>>();
    k_scan_block<<<NB, 256>>>();
    // gemm1 kept at the ncu capture slot (launch right after k_scan_block)
    k_gemm1<<<(NN + 127) / 128, 256, GEMM1_SMEM>>>(x, W1);
    k_scan_top<<<1, 512>>>();
    k_scan_apply<<<NB, 256>>>();
    k_build<<<(NE + 255) / 256, 256>>>(src, dst);
    k_agg1<<<(NN * 32 + 255) / 256, 256>>>();
    k_gemm2<<<NB, 256>>>(W2, b1);
    k_agg2<<<(NN * 32 + 255) / 256, 256>>>(out, b2);
}

// round 16
// speedup vs baseline: 1.5194x; 1.5194x over previous
#include <cuda_runtime.h>

#define NN 100000
#define NE 1600000
#define NB ((NN + 255) / 256)   // 391 blocks for node-sized kernels
#define WS 72                   // padded smem row stride for W1 (floats)

// ---------------- scratch (device globals; no allocation allowed) ----------
__device__ __align__(128) int   g_deg[2 * NN];        // [0,NN): out-deg, [NN,2NN): in-deg
__device__ __align__(128) float g_onorm[NN];
__device__ __align__(128) float g_inorm[NN];
__device__ __align__(128) float g_h1[(size_t)NN * 64];    // (x*onorm)@W1
__device__ __align__(128) float g_agg1[(size_t)NN * 64];  // sum over in-edges of h1[src]
__device__ __align__(128) float g_h2[(size_t)NN * 40];    // layer-2 transformed feats
__device__ __align__(128) int   g_csr[NE];                // src ids grouped by dst
__device__ __align__(128) int   g_rowstart[NN];
__device__ __align__(128) int   g_cursor[NN];
__device__ __align__(128) int   g_bsum[NB + 1];
__device__ __align__(128) int   g_bpre[NB + 1];

// ---------------- packed f32x2 helpers (sm_103a FFMA2 path) -----------------
__device__ __forceinline__ unsigned long long pack2(float x) {
    unsigned long long r;
    asm("mov.b64 %0, {%1, %1};" : "=l"(r) : "f"(x));
    return r;
}
__device__ __forceinline__ void ffma2(unsigned long long& d,
                                      unsigned long long a, unsigned long long b) {
    asm("fma.rn.f32x2 %0, %1, %2, %0;" : "+l"(d) : "l"(a), "l"(b));
}
__device__ __forceinline__ float2 unpack2(unsigned long long v) {
    float2 f;
    asm("mov.b64 {%0, %1}, %2;" : "=f"(f.x), "=f"(f.y) : "l"(v));
    return f;
}

// ---------------- degrees ----------------
__global__ void k_degree(const int* __restrict__ src, const int* __restrict__ dst) {
    int i = blockIdx.x * 256 + threadIdx.x;
    if (i < NE) {
        atomicAdd(&g_deg[__ldg(&src[i])], 1);
        atomicAdd(&g_deg[NN + __ldg(&dst[i])], 1);
    }
}

__global__ void k_norm() {
    int i = blockIdx.x * 256 + threadIdx.x;
    if (i < NN) {
        g_onorm[i] = rsqrtf(fmaxf((float)g_deg[i], 1.0f));
        g_inorm[i] = rsqrtf(fmaxf((float)g_deg[NN + i], 1.0f));
    }
}

// ---------------- CSR build: 3-step block scan of in-degree -----------------
__global__ void k_scan_block() {
    __shared__ int s[256];
    int n = blockIdx.x * 256 + threadIdx.x;
    int v = (n < NN) ? g_deg[NN + n] : 0;
    s[threadIdx.x] = v;
    __syncthreads();
    for (int off = 128; off > 0; off >>= 1) {
        if (threadIdx.x < off) s[threadIdx.x] += s[threadIdx.x + off];
        __syncthreads();
    }
    if (threadIdx.x == 0) g_bsum[blockIdx.x] = s[0];
}

// parallel top-level scan: 1 block, 512 threads (NB=391 fits).
// All shfls run with full-warp participation (divergent masks deadlock).
__global__ void k_scan_top() {
    __shared__ int wsum[16];
    int t = threadIdx.x;
    int lane = t & 31, wid = t >> 5;
    int v = (t < NB) ? g_bsum[t] : 0;
    int x = v;
#pragma unroll
    for (int o = 1; o < 32; o <<= 1) {
        int y = __shfl_up_sync(0xffffffffu, x, o);
        if (lane >= o) x += y;
    }
    if (lane == 31) wsum[wid] = x;
    __syncthreads();
    if (wid == 0) {
        int s = (lane < 16) ? wsum[lane] : 0;
#pragma unroll
        for (int o = 1; o < 16; o <<= 1) {
            int y = __shfl_up_sync(0xffffffffu, s, o);
            if (lane >= o) s += y;
        }
        if (lane < 16) wsum[lane] = s;
    }
    __syncthreads();
    int base = (wid > 0) ? wsum[wid - 1] : 0;
    if (t < NB) g_bpre[t] = base + x - v;   // exclusive prefix of block sums
}

__global__ void k_scan_apply() {
    __shared__ int s[256];
    int n = blockIdx.x * 256 + threadIdx.x;
    int v = (n < NN) ? g_deg[NN + n] : 0;
    s[threadIdx.x] = v;
    __syncthreads();
    for (int off = 1; off < 256; off <<= 1) {
        int t = (threadIdx.x >= off) ? s[threadIdx.x - off] : 0;
        __syncthreads();
        s[threadIdx.x] += t;
        __syncthreads();
    }
    int excl = s[threadIdx.x] - v;
    int rs = g_bpre[blockIdx.x] + excl;
    if (n < NN) { g_rowstart[n] = rs; g_cursor[n] = rs; }
}

__global__ void k_build(const int* __restrict__ src, const int* __restrict__ dst) {
    int e = blockIdx.x * 256 + threadIdx.x;
    if (e < NE) {
        int d = __ldg(&dst[e]);
        int p = atomicAdd(&g_cursor[d], 1);
        g_csr[p] = __ldg(&src[e]);
    }
}

// ---------------- GEMM1: h1 = (x * onorm) @ W1   [100k x 256]@[256 x 64] ----
// R10 structure (measured best: 136.7us) + bank-conflict-free W layout:
// smem row stride 72 floats, columns >=32 shifted +4. Per-warp LDS.128 lane
// offsets become {0,64,144,208}B -> banks {0-3,16-19,4-7,20-23}: disjoint.
__global__ void __launch_bounds__(256, 2)
k_gemm1(const float* __restrict__ x, const float* __restrict__ W1) {
    extern __shared__ float sW[];   // 256 rows * 72 floats = 73.7KB
    for (int i = threadIdx.x; i < 256 * 64; i += 256) {
        int k = i >> 6, j = i & 63;
        sW[k * WS + j + ((j >= 32) ? 4 : 0)] = W1[i];
    }
    __syncthreads();

    int slot = threadIdx.x >> 2;            // 64 node-slots
    int jg = (threadIdx.x & 3) * 16;        // 16-column slice
    int jgo = jg + ((jg >= 32) ? 4 : 0);    // padded base offset
    int nbase = blockIdx.x * 256 + slot * 4;
    if (nbase >= NN) return;

    // clamped row pointers (stores are guarded per node)
    const float4* xr[4];
#pragma unroll
    for (int n = 0; n < 4; n++) {
        int node = nbase + n; if (node >= NN) node = NN - 1;
        xr[n] = reinterpret_cast<const float4*>(x + (size_t)node * 256);
    }

    unsigned long long acc[4][8];           // 4 nodes x 8 col-pairs
#pragma unroll
    for (int n = 0; n < 4; n++)
#pragma unroll
        for (int p = 0; p < 8; p++) acc[n][p] = 0ULL;

#pragma unroll 2
    for (int k4 = 0; k4 < 64; k4++) {
        float4 xv0 = __ldg(&xr[0][k4]);
        float4 xv1 = __ldg(&xr[1][k4]);
        float4 xv2 = __ldg(&xr[2][k4]);
        float4 xv3 = __ldg(&xr[3][k4]);
        float xs0[4] = {xv0.x, xv0.y, xv0.z, xv0.w};
        float xs1[4] = {xv1.x, xv1.y, xv1.z, xv1.w};
        float xs2[4] = {xv2.x, xv2.y, xv2.z, xv2.w};
        float xs3[4] = {xv3.x, xv3.y, xv3.z, xv3.w};
#pragma unroll
        for (int c = 0; c < 4; c++) {
            const ulonglong2* wr =
                reinterpret_cast<const ulonglong2*>(&sW[(k4 * 4 + c) * WS + jgo]);
            ulonglong2 w0 = wr[0];          // cols jg+0..3  (2 f32x2)
            ulonglong2 w1 = wr[1];          // cols jg+4..7
            ulonglong2 w2 = wr[2];          // cols jg+8..11
            ulonglong2 w3 = wr[3];          // cols jg+12..15
            unsigned long long p0 = pack2(xs0[c]);
            unsigned long long p1 = pack2(xs1[c]);
            unsigned long long p2 = pack2(xs2[c]);
            unsigned long long p3 = pack2(xs3[c]);
            ffma2(acc[0][0], p0, w0.x); ffma2(acc[0][1], p0, w0.y);
            ffma2(acc[0][2], p0, w1.x); ffma2(acc[0][3], p0, w1.y);
            ffma2(acc[0][4], p0, w2.x); ffma2(acc[0][5], p0, w2.y);
            ffma2(acc[0][6], p0, w3.x); ffma2(acc[0][7], p0, w3.y);
            ffma2(acc[1][0], p1, w0.x); ffma2(acc[1][1], p1, w0.y);
            ffma2(acc[1][2], p1, w1.x); ffma2(acc[1][3], p1, w1.y);
            ffma2(acc[1][4], p1, w2.x); ffma2(acc[1][5], p1, w2.y);
            ffma2(acc[1][6], p1, w3.x); ffma2(acc[1][7], p1, w3.y);
            ffma2(acc[2][0], p2, w0.x); ffma2(acc[2][1], p2, w0.y);
            ffma2(acc[2][2], p2, w1.x); ffma2(acc[2][3], p2, w1.y);
            ffma2(acc[2][4], p2, w2.x); ffma2(acc[2][5], p2, w2.y);
            ffma2(acc[2][6], p2, w3.x); ffma2(acc[2][7], p2, w3.y);
            ffma2(acc[3][0], p3, w0.x); ffma2(acc[3][1], p3, w0.y);
            ffma2(acc[3][2], p3, w1.x); ffma2(acc[3][3], p3, w1.y);
            ffma2(acc[3][4], p3, w2.x); ffma2(acc[3][5], p3, w2.y);
            ffma2(acc[3][6], p3, w3.x); ffma2(acc[3][7], p3, w3.y);
        }
    }

#pragma unroll
    for (int n = 0; n < 4; n++) {
        int node = nbase + n;
        if (node >= NN) break;
        float nrm = g_onorm[node];
        float4* o = reinterpret_cast<float4*>(&g_h1[(size_t)node * 64 + jg]);
#pragma unroll
        for (int q = 0; q < 4; q++) {
            float2 lo = unpack2(acc[n][q * 2 + 0]);
            float2 hi = unpack2(acc[n][q * 2 + 1]);
            o[q] = make_float4(lo.x * nrm, lo.y * nrm, hi.x * nrm, hi.y * nrm);
        }
    }
}

#define GEMM1_SMEM (256 * WS * 4)

// ---------------- agg1: warp per node, 2 groups of 16, 2x unroll ------------
__global__ void k_agg1() {
    int w = (blockIdx.x * 256 + threadIdx.x) >> 5;
    if (w >= NN) return;
    int lane = threadIdx.x & 31;
    int grp = lane >> 4, c = lane & 15;

    int beg = __ldg(&g_rowstart[w]);
    int end = beg + __ldg(&g_deg[NN + w]);

    float4 a0 = make_float4(0.f, 0.f, 0.f, 0.f);
    float4 a1 = make_float4(0.f, 0.f, 0.f, 0.f);
    int j = beg + grp;
    for (; j + 2 < end; j += 4) {
        int s0 = __ldg(&g_csr[j]);
        int s1 = __ldg(&g_csr[j + 2]);
        float4 v0 = *reinterpret_cast<const float4*>(&g_h1[(size_t)s0 * 64 + c * 4]);
        float4 v1 = *reinterpret_cast<const float4*>(&g_h1[(size_t)s1 * 64 + c * 4]);
        a0.x += v0.x; a0.y += v0.y; a0.z += v0.z; a0.w += v0.w;
        a1.x += v1.x; a1.y += v1.y; a1.z += v1.z; a1.w += v1.w;
    }
    if (j < end) {
        int s0 = __ldg(&g_csr[j]);
        float4 v0 = *reinterpret_cast<const float4*>(&g_h1[(size_t)s0 * 64 + c * 4]);
        a0.x += v0.x; a0.y += v0.y; a0.z += v0.z; a0.w += v0.w;
    }
    float4 acc = make_float4(a0.x + a1.x, a0.y + a1.y, a0.z + a1.z, a0.w + a1.w);

    acc.x += __shfl_down_sync(0xffffffffu, acc.x, 16);
    acc.y += __shfl_down_sync(0xffffffffu, acc.y, 16);
    acc.z += __shfl_down_sync(0xffffffffu, acc.z, 16);
    acc.w += __shfl_down_sync(0xffffffffu, acc.w, 16);
    if (lane < 16)
        *reinterpret_cast<float4*>(&g_agg1[(size_t)w * 64 + c * 4]) = acc;
}

// ---------------- GEMM2 (fused): h2 = ((agg1*inorm + b1) * onorm) @ W2 ------
__global__ void k_gemm2(const float* __restrict__ W2, const float* __restrict__ b1) {
    __shared__ float sW[64 * 40];
    __shared__ float sb[64];
    for (int i = threadIdx.x; i < 64 * 40; i += 256) sW[i] = W2[i];
    if (threadIdx.x < 64) sb[threadIdx.x] = b1[threadIdx.x];
    __syncthreads();

    int n = blockIdx.x * 256 + threadIdx.x;
    if (n >= NN) return;
    float ni = g_inorm[n], no = g_onorm[n];

    float acc[40];
#pragma unroll
    for (int j = 0; j < 40; j++) acc[j] = 0.f;

    const float4* ar = reinterpret_cast<const float4*>(&g_agg1[(size_t)n * 64]);
#pragma unroll 4
    for (int k4 = 0; k4 < 16; k4++) {
        float4 a = ar[k4];
        float av[4] = {a.x, a.y, a.z, a.w};
#pragma unroll
        for (int c = 0; c < 4; c++) {
            int k = k4 * 4 + c;
            float xv = av[c] * ni + sb[k];
            const float4* wr = reinterpret_cast<const float4*>(&sW[k * 40]);
#pragma unroll
            for (int q = 0; q < 10; q++) {
                float4 w = wr[q];
                acc[q * 4 + 0] += xv * w.x;
                acc[q * 4 + 1] += xv * w.y;
                acc[q * 4 + 2] += xv * w.z;
                acc[q * 4 + 3] += xv * w.w;
            }
        }
    }

    float4* o = reinterpret_cast<float4*>(&g_h2[(size_t)n * 40]);
#pragma unroll
    for (int q = 0; q < 10; q++)
        o[q] = make_float4(acc[q*4+0]*no, acc[q*4+1]*no, acc[q*4+2]*no, acc[q*4+3]*no);
}

// ---------------- agg2: warp per node, 3 groups of 10, 2x unroll ------------
__global__ void k_agg2(float* __restrict__ out, const float* __restrict__ b2) {
    int w = (blockIdx.x * 256 + threadIdx.x) >> 5;
    if (w >= NN) return;
    int lane = threadIdx.x & 31;
    int grp = lane / 10;             // 0,1,2 active; lanes 30,31 idle
    int c = lane - grp * 10;

    int beg = __ldg(&g_rowstart[w]);
    int end = beg + __ldg(&g_deg[NN + w]);

    float4 a0 = make_float4(0.f, 0.f, 0.f, 0.f);
    float4 a1 = make_float4(0.f, 0.f, 0.f, 0.f);
    if (grp < 3) {
        int j = beg + grp;
        for (; j + 3 < end; j += 6) {
            int s0 = __ldg(&g_csr[j]);
            int s1 = __ldg(&g_csr[j + 3]);
            float4 v0 = *reinterpret_cast<const float4*>(&g_h2[(size_t)s0 * 40 + c * 4]);
            float4 v1 = *reinterpret_cast<const float4*>(&g_h2[(size_t)s1 * 40 + c * 4]);
            a0.x += v0.x; a0.y += v0.y; a0.z += v0.z; a0.w += v0.w;
            a1.x += v1.x; a1.y += v1.y; a1.z += v1.z; a1.w += v1.w;
        }
        if (j < end) {
            int s0 = __ldg(&g_csr[j]);
            float4 v0 = *reinterpret_cast<const float4*>(&g_h2[(size_t)s0 * 40 + c * 4]);
            a0.x += v0.x; a0.y += v0.y; a0.z += v0.z; a0.w += v0.w;
        }
    }
    float4 acc = make_float4(a0.x + a1.x, a0.y + a1.y, a0.z + a1.z, a0.w + a1.w);

    float ax10 = __shfl_down_sync(0xffffffffu, acc.x, 10);
    float ay10 = __shfl_down_sync(0xffffffffu, acc.y, 10);
    float az10 = __shfl_down_sync(0xffffffffu, acc.z, 10);
    float aw10 = __shfl_down_sync(0xffffffffu, acc.w, 10);
    float ax20 = __shfl_down_sync(0xffffffffu, acc.x, 20);
    float ay20 = __shfl_down_sync(0xffffffffu, acc.y, 20);
    float az20 = __shfl_down_sync(0xffffffffu, acc.z, 20);
    float aw20 = __shfl_down_sync(0xffffffffu, acc.w, 20);
    if (lane < 10) {
        float ni = g_inorm[w];
        float4 bb = __ldg(reinterpret_cast<const float4*>(b2) + c);
        float4 r;
        r.x = (acc.x + ax10 + ax20) * ni + bb.x;
        r.y = (acc.y + ay10 + ay20) * ni + bb.y;
        r.z = (acc.z + az10 + az20) * ni + bb.z;
        r.w = (acc.w + aw10 + aw20) * ni + bb.w;
        *reinterpret_cast<float4*>(out + (size_t)w * 40 + c * 4) = r;
    }
}

extern "C" void kernel_launch(void* const* d_in, const int* in_sizes, int n_in,
                              void* d_out, int out_size) {
    const float* x   = (const float*)d_in[0];
    const int*   src = (const int*)d_in[1];
    const int*   dst = (const int*)d_in[2];
    const float* W1  = (const float*)d_in[3];
    const float* b1  = (const float*)d_in[4];
    const float* W2  = (const float*)d_in[5];
    const float* b2  = (const float*)d_in[6];
    float* out = (float*)d_out;

    void* p_deg;
    cudaGetSymbolAddress(&p_deg, g_deg);
    cudaMemsetAsync(p_deg, 0, sizeof(int) * 2 * NN, 0);

    cudaFuncSetAttribute(k_gemm1, cudaFuncAttributeMaxDynamicSharedMemorySize, GEMM1_SMEM);

    k_degree<<<(NE + 255) / 256, 256>>>(src, dst);
    k_norm<<<NB, 256>>>();
    k_scan_block<<<NB, 256>>>();
    // gemm1 kept at the ncu capture slot (launch right after k_scan_block)
    k_gemm1<<<(NN + 255) / 256, 256, GEMM1_SMEM>>>(x, W1);
    k_scan_top<<<1, 512>>>();
    k_scan_apply<<<NB, 256>>>();
    k_build<<<(NE + 255) / 256, 256>>>(src, dst);
    k_agg1<<<(NN * 32 + 255) / 256, 256>>>();
    k_gemm2<<<NB, 256>>>(W2, b1);
    k_agg2<<<(NN * 32 + 255) / 256, 256>>>(out, b2);
}